// round 7
// baseline (speedup 1.0000x reference)
#include <cuda_runtime.h>

// CRZ (DIM=2, WIRES=12, control=0, target=1, J=1): diagonal unitary, phase
// depends only on the top two bits of row n (n in [0,4096)), BATCH=2048.
//   region 0,1 (n < 2048)        : d = 1
//   region 2   (2048 <= n < 3072): d = exp(-i*a),  a = 0.5 * angle
//   region 3   (3072 <= n < 4096): d = exp(+i*a)
// Harness output is FLOAT32 [D*BATCH] = real part:
//   out[n,b] = re*pc - im*ps.
//
// R6 -> R7: 4 float4 per thread (MLP_p1=8) + streaming stores (__stcs) so
// the 33.5MB output stream doesn't evict the 64MB of inputs from L2 across
// graph replays.

#define D_DIM   4096
#define BATCH   2048
#define TOTAL   (D_DIM * BATCH)    // 8388608 float32 elements
#define VEC     (TOTAL / 4)        // 2097152 float4 units
#define PER_T   4                  // float4s per thread
#define NTHREAD (VEC / PER_T)      // 524288 threads

__global__ __launch_bounds__(256) void crz_kernel(
    const float4* __restrict__ xre,
    const float4* __restrict__ xim,
    const float*  __restrict__ angle,
    float4*       __restrict__ out)
{
    int t = blockIdx.x * blockDim.x + threadIdx.x;
    if (t >= NTHREAD) return;

    int base = t * PER_T;               // first float4 index
    // elements 16t..16t+15 span one row (BATCH=2048 divisible by 16):
    // row = (16t) >> 11 = t >> 7 ; region = row >> 10 = t >> 17
    int region = t >> 17;               // 0..3

    float a = (angle != nullptr) ? 0.5f * angle[0] : 0.0f;
    float s, c;
    __sincosf(a, &s, &c);

    float pc = (region >= 2) ? c : 1.0f;
    float ps = (region == 2) ? -s : ((region == 3) ? s : 0.0f);

    // Front-batch all 8 loads for maximum MLP.
    float4 re0 = xre[base + 0];
    float4 re1 = xre[base + 1];
    float4 re2 = xre[base + 2];
    float4 re3 = xre[base + 3];
    float4 im0 = xim[base + 0];
    float4 im1 = xim[base + 1];
    float4 im2 = xim[base + 2];
    float4 im3 = xim[base + 3];

    float4 o0, o1, o2, o3;
    o0.x = fmaf(re0.x, pc, -im0.x * ps);
    o0.y = fmaf(re0.y, pc, -im0.y * ps);
    o0.z = fmaf(re0.z, pc, -im0.z * ps);
    o0.w = fmaf(re0.w, pc, -im0.w * ps);
    o1.x = fmaf(re1.x, pc, -im1.x * ps);
    o1.y = fmaf(re1.y, pc, -im1.y * ps);
    o1.z = fmaf(re1.z, pc, -im1.z * ps);
    o1.w = fmaf(re1.w, pc, -im1.w * ps);
    o2.x = fmaf(re2.x, pc, -im2.x * ps);
    o2.y = fmaf(re2.y, pc, -im2.y * ps);
    o2.z = fmaf(re2.z, pc, -im2.z * ps);
    o2.w = fmaf(re2.w, pc, -im2.w * ps);
    o3.x = fmaf(re3.x, pc, -im3.x * ps);
    o3.y = fmaf(re3.y, pc, -im3.y * ps);
    o3.z = fmaf(re3.z, pc, -im3.z * ps);
    o3.w = fmaf(re3.w, pc, -im3.w * ps);

    // Streaming stores: evict-first in L2 so inputs stay resident.
    __stcs(&out[base + 0], o0);
    __stcs(&out[base + 1], o1);
    __stcs(&out[base + 2], o2);
    __stcs(&out[base + 3], o3);
}

extern "C" void kernel_launch(void* const* d_in, const int* in_sizes, int n_in,
                              void* d_out, int out_size)
{
    // Size-based mapping: size-1 tensor is angle; the two TOTAL-sized tensors
    // are (x_real, x_imag) in original relative order. Positional fallback.
    const float* angle = nullptr;
    const void* planes[2] = {nullptr, nullptr};
    int np = 0;
    for (int i = 0; i < n_in; i++) {
        if (in_sizes[i] == 1) {
            if (angle == nullptr) angle = (const float*)d_in[i];
        } else if (in_sizes[i] == TOTAL && np < 2) {
            planes[np++] = d_in[i];
        }
    }
    if (np < 2) {
        np = 0;
        for (int i = 0; i < n_in && np < 2; i++)
            if (in_sizes[i] > 1) planes[np++] = d_in[i];
    }
    if (np < 2) return;

    int threads = 256;
    int blocks  = NTHREAD / threads;    // 2048 blocks
    crz_kernel<<<blocks, threads>>>(
        (const float4*)planes[0],
        (const float4*)planes[1],
        angle,
        (float4*)d_out);
}

// round 9
// speedup vs baseline: 1.4545x; 1.4545x over previous
#include <cuda_runtime.h>

// CRZ (DIM=2, WIRES=12, control=0, target=1, J=1): diagonal unitary, phase
// depends only on the top two bits of row n (n in [0,4096)), BATCH=2048.
//   region 0,1 (n < 2048)        : d = 1
//   region 2   (2048 <= n < 3072): d = exp(-i*a),  a = 0.5 * angle
//   region 3   (3072 <= n < 4096): d = exp(+i*a)
// Harness output is FLOAT32 [D*BATCH] = real part:
//   out[n,b] = re*pc - im*ps.
//
// R7 -> R8: same 4-float4-per-thread ILP, but BLOCK-STRIDED so each warp
// LDG.128/STG.128 is fully coalesced (R7's thread-contiguous layout made
// every warp access span 16 cache lines -> L1tex replays, 40% DRAM).
// Keep __stcs streaming stores (output must not evict inputs from L2).

#define D_DIM   4096
#define BATCH   2048
#define TOTAL   (D_DIM * BATCH)    // 8388608 float32 elements
#define VEC     (TOTAL / 4)        // 2097152 float4 units
#define THREADS 256
#define PER_T   4                  // float4s per thread
#define F4_PER_BLOCK (THREADS * PER_T)   // 1024 float4 = 4096 elems = 2 rows

__global__ __launch_bounds__(THREADS) void crz_kernel(
    const float4* __restrict__ xre,
    const float4* __restrict__ xim,
    const float*  __restrict__ angle,
    float4*       __restrict__ out)
{
    int base = blockIdx.x * F4_PER_BLOCK + threadIdx.x;

    // Block covers elements [blockIdx*4096, +4096); region = elem >> 21
    // -> region = blockIdx >> 9 (uniform across the block).
    int region = blockIdx.x >> 9;      // 0..3

    float a = (angle != nullptr) ? 0.5f * angle[0] : 0.0f;
    float s, c;
    __sincosf(a, &s, &c);

    float pc = (region >= 2) ? c : 1.0f;
    float ps = (region == 2) ? -s : ((region == 3) ? s : 0.0f);

    // Front-batched, fully coalesced loads (8 outstanding LDG.128).
    float4 re0 = xre[base + 0 * THREADS];
    float4 re1 = xre[base + 1 * THREADS];
    float4 re2 = xre[base + 2 * THREADS];
    float4 re3 = xre[base + 3 * THREADS];
    float4 im0 = xim[base + 0 * THREADS];
    float4 im1 = xim[base + 1 * THREADS];
    float4 im2 = xim[base + 2 * THREADS];
    float4 im3 = xim[base + 3 * THREADS];

    float4 o0, o1, o2, o3;
    o0.x = fmaf(re0.x, pc, -im0.x * ps);
    o0.y = fmaf(re0.y, pc, -im0.y * ps);
    o0.z = fmaf(re0.z, pc, -im0.z * ps);
    o0.w = fmaf(re0.w, pc, -im0.w * ps);
    o1.x = fmaf(re1.x, pc, -im1.x * ps);
    o1.y = fmaf(re1.y, pc, -im1.y * ps);
    o1.z = fmaf(re1.z, pc, -im1.z * ps);
    o1.w = fmaf(re1.w, pc, -im1.w * ps);
    o2.x = fmaf(re2.x, pc, -im2.x * ps);
    o2.y = fmaf(re2.y, pc, -im2.y * ps);
    o2.z = fmaf(re2.z, pc, -im2.z * ps);
    o2.w = fmaf(re2.w, pc, -im2.w * ps);
    o3.x = fmaf(re3.x, pc, -im3.x * ps);
    o3.y = fmaf(re3.y, pc, -im3.y * ps);
    o3.z = fmaf(re3.z, pc, -im3.z * ps);
    o3.w = fmaf(re3.w, pc, -im3.w * ps);

    // Streaming (evict-first) stores, fully coalesced.
    __stcs(&out[base + 0 * THREADS], o0);
    __stcs(&out[base + 1 * THREADS], o1);
    __stcs(&out[base + 2 * THREADS], o2);
    __stcs(&out[base + 3 * THREADS], o3);
}

extern "C" void kernel_launch(void* const* d_in, const int* in_sizes, int n_in,
                              void* d_out, int out_size)
{
    // Size-based mapping: size-1 tensor is angle; the two TOTAL-sized tensors
    // are (x_real, x_imag) in original relative order. Positional fallback.
    const float* angle = nullptr;
    const void* planes[2] = {nullptr, nullptr};
    int np = 0;
    for (int i = 0; i < n_in; i++) {
        if (in_sizes[i] == 1) {
            if (angle == nullptr) angle = (const float*)d_in[i];
        } else if (in_sizes[i] == TOTAL && np < 2) {
            planes[np++] = d_in[i];
        }
    }
    if (np < 2) {
        np = 0;
        for (int i = 0; i < n_in && np < 2; i++)
            if (in_sizes[i] > 1) planes[np++] = d_in[i];
    }
    if (np < 2) return;

    int blocks = VEC / F4_PER_BLOCK;    // 2048 blocks
    crz_kernel<<<blocks, THREADS>>>(
        (const float4*)planes[0],
        (const float4*)planes[1],
        angle,
        (float4*)d_out);
}